// round 15
// baseline (speedup 1.0000x reference)
#include <cuda_runtime.h>
#include <cstdint>

#define NN     7680
#define NASM   256
#define CAPA   30
#define BATCH  64
#define KMAX   8
#define NTM    512
#define RPTM   15      // NN / NTM
#define NWARP  16
#define MAXC   960
#define S1BLK  960     // step1: 15 chunks x 64 samples
#define NN4    (NN / 4)
#define QCH    8       // colnorm source-chunk

// dynamic smem layout (bytes): [0,7680) cand/sc8 union, [7680,38400) sinvc,
// [38400,69120) srb
#define SMEM_DYN_BYTES (7680 + 30720 + 30720)

__device__ float         g_invc[NN];
__device__ unsigned char g_scores8[BATCH][NN];
__device__ unsigned int  g_rowbits[NN];

static __device__ __forceinline__ unsigned long long make_key(float v, int j){
    // v > 0. Bigger value -> bigger key; equal value -> smaller j wins.
    return (((unsigned long long)__float_as_uint(v)) << 32) | (unsigned int)(NN - 1 - j);
}
static __device__ __forceinline__ int key_j(unsigned long long k){
    return NN - 1 - (int)(k & 0xffffffffull);
}

// ---------------------------------------------------------------------------
// Fused prep (unchanged from R13 winner):
//  blocks [0,960):      step1 scores (uint8 exact counts), dedup by s[b]
//  blocks [960,1216):   colnorm + rowbits, gather-parallel
// ---------------------------------------------------------------------------
__global__ void __launch_bounds__(128) prep_kernel(
    const int* __restrict__ p, const int* __restrict__ s,
    const float* __restrict__ W_in, const float* __restrict__ W_rec)
{
    const int bid = blockIdx.x;
    const int tid = threadIdx.x;
    if (bid < S1BLK){
        __shared__ int ss[BATCH];
        const int b = bid / 15;
        if (tid < BATCH) ss[tid] = s[tid];
        __syncthreads();
        const int sb = ss[b];
        bool dup = false;
        for (int b2 = 0; b2 < b; ++b2) dup |= (ss[b2] == sb);
        if (dup) return;                              // representative writes instead

        const int c4 = (bid % 15) * 128 + tid;        // float4 index 0..1919
        const float4* src = (const float4*)(W_in + (size_t)sb * CAPA * NN) + c4;
        float ax = 0.f, ay = 0.f, az = 0.f, aw = 0.f;
        #pragma unroll 1
        for (int g = 0; g < 3; ++g){                  // 10 loads in flight per group
            float4 w[10];
            #pragma unroll
            for (int uu = 0; uu < 10; ++uu)
                w[uu] = __ldg(src + (size_t)(g * 10 + uu) * NN4);
            #pragma unroll
            for (int uu = 0; uu < 10; ++uu){          // integer counts: exact any order
                ax += w[uu].x; ay += w[uu].y; az += w[uu].z; aw += w[uu].w;
            }
        }
        uchar4 r;
        r.x = (unsigned char)(int)ax; r.y = (unsigned char)(int)ay;
        r.z = (unsigned char)(int)az; r.w = (unsigned char)(int)aw;
        ((uchar4*)g_scores8[b])[c4] = r;
    } else {
        // ---- colnorm + rowbits for destination assembly a ------------------
        __shared__ int      sp2[NASM];
        __shared__ int      qlist[NASM];
        __shared__ unsigned rbl[QCH * CAPA];
        __shared__ int      cnt[CAPA];
        __shared__ int      snq;
        const int a = bid - S1BLK;
        sp2[tid]       = p[tid];
        sp2[tid + 128] = p[tid + 128];
        if (tid < CAPA) cnt[tid] = 0;
        __syncthreads();
        if (tid < 32){                                // warp 0: sources pointing to a
            int run = 0;
            for (int g = 0; g < 8; ++g){
                bool m = (sp2[g * 32 + tid] == a);
                unsigned bal = __ballot_sync(0xffffffffu, m);
                if (m) qlist[run + __popc(bal & ((1u << tid) - 1u))] = g * 32 + tid;
                run += __popc(bal);
            }
            if (tid == 0) snq = run;
        }
        __syncthreads();
        const int nq = snq;
        for (int c0 = 0; c0 < nq; c0 += QCH){
            const int nqc   = min(QCH, nq - c0);
            const int tasks = nqc * CAPA;
            for (int i = tid; i < tasks; i += 128){
                int qi = i / CAPA, m = i % CAPA;
                int q  = qlist[c0 + qi];
                const float* row = W_rec + (size_t)(q * CAPA + m) * NN + a * CAPA;
                unsigned bits = 0;
                #pragma unroll
                for (int c = 0; c < CAPA; ++c)
                    if (row[c] != 0.f) bits |= (1u << c);
                rbl[i] = bits;
                g_rowbits[q * CAPA + m] = bits;
            }
            __syncthreads();
            if (tid < CAPA){
                int add = 0;
                for (int w = 0; w < tasks; ++w) add += (rbl[w] >> tid) & 1;
                cnt[tid] += add;
            }
            __syncthreads();
        }
        if (tid < CAPA) g_invc[a * CAPA + tid] = 1.0f / fmaxf((float)cnt[tid], 1e-6f);
    }
}

// ---------------------------------------------------------------------------
// Main: one block per sample; 512 threads; atomic-free chase path.
// ---------------------------------------------------------------------------
__global__ void __launch_bounds__(NTM) pointer_ac_kernel(
    const int* __restrict__ p, const int* __restrict__ s,
    const int* __restrict__ k, float* __restrict__ out)
{
    extern __shared__ char dyn[];
    unsigned long long* cand = (unsigned long long*)dyn;      // [MAXC], chase phase
    unsigned char*      sc8  = (unsigned char*)dyn;           // [NN], kWTA phase (union)
    float*              sinvc = (float*)(dyn + 7680);         // [NN]
    unsigned int*       srb   = (unsigned int*)(dyn + 38400); // [NN]

    __shared__ int   warpHist[NWARP * 31];
    __shared__ int   hist[31];
    __shared__ int   sp[NASM];
    __shared__ int   ssamp[BATCH];
    __shared__ int   scnt[NASM];
    __shared__ int   sel[CAPA];
    __shared__ int   wcnt[CAPA];                      // per-target candidate counts
    __shared__ unsigned int warb[NWARP][CAPA];        // per-warp rowbits slots
    __shared__ int   warpSumG[NWARP], warpSumT[NWARP];
    __shared__ int   warpOffG[NWARP], warpOffT[NWARP];
    __shared__ int   sT, sNG, sbesta;

    const int b    = blockIdx.x;
    const int tid  = threadIdx.x;
    const int lane = tid & 31;
    const int wid  = tid >> 5;

    if (tid < NASM) sp[tid] = p[tid];
    if (tid < BATCH) ssamp[tid] = s[tid];
    const int kb = __ldg(&k[b]);
    if (tid < NWARP * 31) warpHist[tid] = 0;

    #pragma unroll
    for (int r = 0; r < 4; ++r){                      // sinvc: 1920 float4
        int i = tid + r * NTM;
        if (i < NN4) ((float4*)sinvc)[i] = ((const float4*)g_invc)[i];
    }
    #pragma unroll
    for (int r = 0; r < 4; ++r){                      // srb: 1920 uint4
        int i = tid + r * NTM;
        if (i < NN4) ((uint4*)srb)[i] = ((const uint4*)g_rowbits)[i];
    }
    __syncthreads();

    // representative sample (first occurrence of s[b]) holds the scores
    int rep = b;
    for (int b2 = 0; b2 < BATCH; ++b2){
        if (ssamp[b2] == ssamp[b]){ rep = b2; break; }
    }
    if (tid < NN / 16)                                // sc8: 480 uint4 (byte array)
        ((uint4*)sc8)[tid] = ((const uint4*)g_scores8[rep])[tid];
    __syncthreads();

    // ====== dense kWTA via histogram (exact ints 0..30), atomic-free slots ==
    {
        int* myh = warpHist + wid * 31;
        const int base_j = tid * RPTM;                // contiguous segment
        #pragma unroll
        for (int i = 0; i < RPTM; ++i){
            int v = sc8[base_j + i];
            atomicAdd(&myh[v], 1);
        }
        __syncthreads();
        if (tid < 31){
            int c = 0;
            #pragma unroll
            for (int w = 0; w < NWARP; ++w) c += warpHist[w * 31 + tid];
            hist[tid] = c;
        }
        __syncthreads();
        if (tid == 0){
            int suf = 0, T = 0, ng = 0;
            for (int v = 30; v >= 0; --v){
                suf += hist[v];
                if (suf >= CAPA){ T = v; ng = suf - hist[v]; break; }
            }
            sT = T; sNG = ng;
        }
        __syncthreads();
        const int T    = sT;
        const int ng   = sNG;
        const int need = CAPA - ng;

        int cntG = 0, cntT = 0;
        #pragma unroll
        for (int i = 0; i < RPTM; ++i){
            int v = sc8[base_j + i];
            cntG += (v > T);
            cntT += (v == T);
        }
        int inclG = cntG, inclT = cntT;
        #pragma unroll
        for (int o = 1; o < 32; o <<= 1){
            int nG = __shfl_up_sync(0xffffffffu, inclG, o);
            int nT = __shfl_up_sync(0xffffffffu, inclT, o);
            if (lane >= o){ inclG += nG; inclT += nT; }
        }
        if (lane == 31){ warpSumG[wid] = inclG; warpSumT[wid] = inclT; }
        __syncthreads();
        if (tid == 0){
            int runG = 0, runT = 0;
            #pragma unroll
            for (int w = 0; w < NWARP; ++w){
                warpOffG[w] = runG; runG += warpSumG[w];
                warpOffT[w] = runT; runT += warpSumT[w];
            }
        }
        __syncthreads();
        int slotG = warpOffG[wid] + inclG - cntG;
        int slotT = warpOffT[wid] + inclT - cntT;

        #pragma unroll
        for (int i = 0; i < RPTM; ++i){
            int j = base_j + i;
            int v = sc8[j];
            if (v > T){
                sel[slotG++] = j;                     // deterministic, j-ascending
            } else if (v == T){
                if (slotT < need) sel[ng + slotT] = j;
                ++slotT;
            }
        }
        __syncthreads();
    }

    // ====== recurrent pointer-chase: 2 barriers/step, no atomics ============
    for (int t = 0; t < KMAX; ++t){
        if (t >= kb) break;                           // uniform per block

        // Phase A: every warp, registers + warp-private rowbits slot
        int an = (lane < CAPA) ? sel[lane] : 0;
        int tg = (lane < CAPA) ? sp[an / CAPA] : (256 + lane);
        unsigned mm = __match_any_sync(0xffffffffu, tg);
        if (lane < CAPA) warb[wid][lane] = srb[an];
        bool leader = (lane < CAPA) && ((int)(__ffs(mm) - 1) == lane);
        unsigned lb = __ballot_sync(0xffffffffu, leader);
        const int ntg = __popc(lb);
        __syncwarp();

        // Phase B: warp handles targets {wid, wid+16}; deterministic slots
        for (int ti = wid; ti < CAPA; ti += NWARP){
            int nc2 = 0;
            if (ti < ntg){
                int ldr = __fns(lb, 0, ti + 1);       // lane of ti-th leader
                unsigned srcs = __shfl_sync(0xffffffffu, mm, ldr);
                int a         = __shfl_sync(0xffffffffu, tg, ldr);
                int j = a * CAPA + lane;
                float ic = (lane < CAPA) ? sinvc[j] : 0.f;
                float vv = 0.f;
                while (srcs){                         // equal-term adds: order-free
                    int m = __ffs(srcs) - 1; srcs &= srcs - 1;
                    if ((warb[wid][m] >> lane) & 1u) vv += ic;
                }
                bool pos = (lane < CAPA) && (vv > 0.f);
                unsigned bal = __ballot_sync(0xffffffffu, pos);
                if (pos)
                    cand[ti * 32 + __popc(bal & ((1u << lane) - 1u))] = make_key(vv, j);
                nc2 = __popc(bal);
            }
            if (lane == 0) wcnt[ti] = nc2;
        }
        __syncthreads();                              // BAR 1: cand/wcnt complete

        // Phase C: rank-select top-30 over sparse slots (+ zero fill)
        for (int slot = tid; slot < CAPA * 32; slot += NTM){
            int ti = slot >> 5, i = slot & 31;
            if (i < wcnt[ti]){
                unsigned long long kq = cand[slot];
                int rank = 0;
                for (int tj = 0; tj < CAPA; ++tj){
                    int wc = wcnt[tj];
                    for (int x = 0; x < wc; ++x) rank += (cand[tj * 32 + x] > kq);
                }
                if (rank < CAPA) sel[rank] = key_j(kq);
            }
        }
        if (tid == 0){
            int nc = 0;
            #pragma unroll
            for (int tj = 0; tj < CAPA; ++tj) nc += wcnt[tj];
            if (nc < CAPA){
                int P = nc, j = 0;
                while (P < CAPA){
                    bool ispos = false;
                    for (int tj = 0; tj < CAPA; ++tj){
                        int wc = wcnt[tj];
                        for (int x = 0; x < wc; ++x)
                            ispos |= (key_j(cand[tj * 32 + x]) == j);
                    }
                    if (!ispos) sel[P++] = j;
                    ++j;
                }
            }
        }
        __syncthreads();                              // BAR 2: sel ready
    }

    // ====== overlaps -> argmax (warp 0 reduce) -> one-hot ===================
    if (tid < NASM) scnt[tid] = 0;
    __syncthreads();
    if (tid < CAPA) atomicAdd(&scnt[sel[tid] / CAPA], 1);
    __syncthreads();
    if (wid == 0){
        unsigned long long bk = 0;
        #pragma unroll
        for (int r = 0; r < NASM / 32; ++r){
            int a = lane + r * 32;
            unsigned long long key =
                (((unsigned long long)scnt[a]) << 32) | (unsigned)(NASM - 1 - a);
            if (key > bk) bk = key;                   // max count, then smallest a
        }
        #pragma unroll
        for (int o = 16; o > 0; o >>= 1){
            unsigned long long obk = __shfl_xor_sync(0xffffffffu, bk, o);
            if (obk > bk) bk = obk;
        }
        if (lane == 0) sbesta = NASM - 1 - (int)(bk & 0xffffffffull);
    }
    __syncthreads();
    if (tid < NASM) out[(size_t)b * NASM + tid] = (tid == sbesta) ? 1.0f : 0.0f;
}

// ---------------------------------------------------------------------------
extern "C" void kernel_launch(void* const* d_in, const int* in_sizes, int n_in,
                              void* d_out, int out_size)
{
    const int*   p     = (const int*)d_in[0];     // [256]
    const int*   s     = (const int*)d_in[1];     // [64]
    const int*   k     = (const int*)d_in[2];     // [64]
    const float* W_in  = (const float*)d_in[3];   // [7680*7680]
    const float* W_rec = (const float*)d_in[4];   // [7680*7680]
    float*       out   = (float*)d_out;           // [64*256]

    cudaFuncSetAttribute(pointer_ac_kernel,
                         cudaFuncAttributeMaxDynamicSharedMemorySize, SMEM_DYN_BYTES);
    prep_kernel<<<S1BLK + NASM, 128>>>(p, s, W_in, W_rec);
    pointer_ac_kernel<<<BATCH, NTM, SMEM_DYN_BYTES>>>(p, s, k, out);
}

// round 16
// speedup vs baseline: 1.4149x; 1.4149x over previous
#include <cuda_runtime.h>
#include <cstdint>

#define NN     7680
#define NASM   256
#define CAPA   30
#define BATCH  64
#define KMAX   8
#define NTM    512
#define RPTM   15      // NN / NTM
#define NWARP  16
#define MAXC   960
#define S1BLK  960     // step1: 15 chunks x 64 samples
#define NN4    (NN / 4)
#define QCH    8       // colnorm source-chunk

// dynamic smem layout (bytes): [0,7680) cand/sc8 union, [7680,38400) sinvc,
// [38400,69120) srb
#define SMEM_DYN_BYTES (7680 + 30720 + 30720)

__device__ float         g_invc[NN];
__device__ unsigned char g_scores8[BATCH][NN];
__device__ unsigned int  g_rowbits[NN];

static __device__ __forceinline__ unsigned long long make_key(float v, int j){
    // v > 0. Bigger value -> bigger key; equal value -> smaller j wins.
    return (((unsigned long long)__float_as_uint(v)) << 32) | (unsigned int)(NN - 1 - j);
}
static __device__ __forceinline__ int key_j(unsigned long long k){
    return NN - 1 - (int)(k & 0xffffffffull);
}

// ---------------------------------------------------------------------------
// Fused prep (unchanged from R13 winner):
//  blocks [0,960):      step1 scores (uint8 exact counts), dedup by s[b]
//  blocks [960,1216):   colnorm + rowbits, gather-parallel
// ---------------------------------------------------------------------------
__global__ void __launch_bounds__(128) prep_kernel(
    const int* __restrict__ p, const int* __restrict__ s,
    const float* __restrict__ W_in, const float* __restrict__ W_rec)
{
    const int bid = blockIdx.x;
    const int tid = threadIdx.x;
    if (bid < S1BLK){
        __shared__ int ss[BATCH];
        const int b = bid / 15;
        if (tid < BATCH) ss[tid] = s[tid];
        __syncthreads();
        const int sb = ss[b];
        bool dup = false;
        for (int b2 = 0; b2 < b; ++b2) dup |= (ss[b2] == sb);
        if (dup) return;                              // representative writes instead

        const int c4 = (bid % 15) * 128 + tid;        // float4 index 0..1919
        const float4* src = (const float4*)(W_in + (size_t)sb * CAPA * NN) + c4;
        float ax = 0.f, ay = 0.f, az = 0.f, aw = 0.f;
        #pragma unroll 1
        for (int g = 0; g < 3; ++g){                  // 10 loads in flight per group
            float4 w[10];
            #pragma unroll
            for (int uu = 0; uu < 10; ++uu)
                w[uu] = __ldg(src + (size_t)(g * 10 + uu) * NN4);
            #pragma unroll
            for (int uu = 0; uu < 10; ++uu){          // integer counts: exact any order
                ax += w[uu].x; ay += w[uu].y; az += w[uu].z; aw += w[uu].w;
            }
        }
        uchar4 r;
        r.x = (unsigned char)(int)ax; r.y = (unsigned char)(int)ay;
        r.z = (unsigned char)(int)az; r.w = (unsigned char)(int)aw;
        ((uchar4*)g_scores8[b])[c4] = r;
    } else {
        // ---- colnorm + rowbits for destination assembly a ------------------
        __shared__ int      sp2[NASM];
        __shared__ int      qlist[NASM];
        __shared__ unsigned rbl[QCH * CAPA];
        __shared__ int      cnt[CAPA];
        __shared__ int      snq;
        const int a = bid - S1BLK;
        sp2[tid]       = p[tid];
        sp2[tid + 128] = p[tid + 128];
        if (tid < CAPA) cnt[tid] = 0;
        __syncthreads();
        if (tid < 32){                                // warp 0: sources pointing to a
            int run = 0;
            for (int g = 0; g < 8; ++g){
                bool m = (sp2[g * 32 + tid] == a);
                unsigned bal = __ballot_sync(0xffffffffu, m);
                if (m) qlist[run + __popc(bal & ((1u << tid) - 1u))] = g * 32 + tid;
                run += __popc(bal);
            }
            if (tid == 0) snq = run;
        }
        __syncthreads();
        const int nq = snq;
        for (int c0 = 0; c0 < nq; c0 += QCH){
            const int nqc   = min(QCH, nq - c0);
            const int tasks = nqc * CAPA;
            for (int i = tid; i < tasks; i += 128){
                int qi = i / CAPA, m = i % CAPA;
                int q  = qlist[c0 + qi];
                const float* row = W_rec + (size_t)(q * CAPA + m) * NN + a * CAPA;
                unsigned bits = 0;
                #pragma unroll
                for (int c = 0; c < CAPA; ++c)
                    if (row[c] != 0.f) bits |= (1u << c);
                rbl[i] = bits;
                g_rowbits[q * CAPA + m] = bits;
            }
            __syncthreads();
            if (tid < CAPA){
                int add = 0;
                for (int w = 0; w < tasks; ++w) add += (rbl[w] >> tid) & 1;
                cnt[tid] += add;
            }
            __syncthreads();
        }
        if (tid < CAPA) g_invc[a * CAPA + tid] = 1.0f / fmaxf((float)cnt[tid], 1e-6f);
    }
}

// ---------------------------------------------------------------------------
// Main: one block per sample; R13 structure; reduced shared-atomic traffic.
// ---------------------------------------------------------------------------
__global__ void __launch_bounds__(NTM) pointer_ac_kernel(
    const int* __restrict__ p, const int* __restrict__ s,
    const int* __restrict__ k, float* __restrict__ out)
{
    extern __shared__ char dyn[];
    unsigned long long* cand = (unsigned long long*)dyn;      // [MAXC], chase phase
    unsigned char*      sc8  = (unsigned char*)dyn;           // [NN], kWTA phase (union)
    float*              sinvc = (float*)(dyn + 7680);         // [NN]
    unsigned int*       srb   = (unsigned int*)(dyn + 38400); // [NN]

    __shared__ int   warpHist[NWARP * 31];
    __shared__ int   hist[31];
    __shared__ int   sp[NASM];
    __shared__ int   ssamp[BATCH];
    __shared__ int   scnt[NASM];
    __shared__ int   sel[CAPA];
    __shared__ int   tgtl[CAPA];
    __shared__ unsigned int smask[CAPA];
    __shared__ unsigned int arb[CAPA];
    __shared__ int   warpSum[NWARP], warpOff[NWARP];
    __shared__ int   sT, sNG, sticket, sncand, sntgt, sbesta;

    const int b    = blockIdx.x;
    const int tid  = threadIdx.x;
    const int lane = tid & 31;
    const int wid  = tid >> 5;

    if (tid < NASM) sp[tid] = p[tid];
    if (tid < BATCH) ssamp[tid] = s[tid];
    const int kb = __ldg(&k[b]);
    if (tid < NWARP * 31) warpHist[tid] = 0;
    if (tid == 0) sticket = 0;

    #pragma unroll
    for (int r = 0; r < 4; ++r){                      // sinvc: 1920 float4
        int i = tid + r * NTM;
        if (i < NN4) ((float4*)sinvc)[i] = ((const float4*)g_invc)[i];
    }
    #pragma unroll
    for (int r = 0; r < 4; ++r){                      // srb: 1920 uint4
        int i = tid + r * NTM;
        if (i < NN4) ((uint4*)srb)[i] = ((const uint4*)g_rowbits)[i];
    }
    __syncthreads();

    // representative sample (first occurrence of s[b]) holds the scores
    int rep = b;
    for (int b2 = 0; b2 < BATCH; ++b2){
        if (ssamp[b2] == ssamp[b]){ rep = b2; break; }
    }
    if (tid < NN / 16)                                // sc8: 480 uint4 (byte array)
        ((uint4*)sc8)[tid] = ((const uint4*)g_scores8[rep])[tid];
    __syncthreads();

    // ====== dense kWTA via histogram (exact ints 0..30) =====================
    {
        int* myh = warpHist + wid * 31;
        const int base_j = tid * RPTM;                // contiguous segment
        #pragma unroll
        for (int i = 0; i < RPTM; ++i){
            int v = sc8[base_j + i];
            // leader-aggregated, conflict-free per-warp histogram update
            unsigned mm = __match_any_sync(0xffffffffu, v);
            if ((int)(__ffs(mm) - 1) == lane) myh[v] += __popc(mm);
        }
        __syncthreads();
        if (tid < 31){
            int c = 0;
            #pragma unroll
            for (int w = 0; w < NWARP; ++w) c += warpHist[w * 31 + tid];
            hist[tid] = c;
        }
        __syncthreads();
        if (tid == 0){
            int suf = 0, T = 0, ng = 0;
            for (int v = 30; v >= 0; --v){
                suf += hist[v];
                if (suf >= CAPA){ T = v; ng = suf - hist[v]; break; }
            }
            sT = T; sNG = ng;
        }
        __syncthreads();
        const int T    = sT;
        const int ng   = sNG;
        const int need = CAPA - ng;

        int cntT = 0;
        #pragma unroll
        for (int i = 0; i < RPTM; ++i) cntT += (sc8[base_j + i] == T);
        int incl = cntT;
        #pragma unroll
        for (int o = 1; o < 32; o <<= 1){
            int n = __shfl_up_sync(0xffffffffu, incl, o);
            if (lane >= o) incl += n;
        }
        if (lane == 31) warpSum[wid] = incl;
        __syncthreads();
        if (tid == 0){
            int run = 0;
            #pragma unroll
            for (int w = 0; w < NWARP; ++w){ warpOff[w] = run; run += warpSum[w]; }
        }
        __syncthreads();
        int slotT = warpOff[wid] + incl - cntT;

        #pragma unroll
        for (int i = 0; i < RPTM; ++i){
            int j = base_j + i;
            int v = sc8[j];
            if (v > T){
                int sl = atomicAdd(&sticket, 1);      // rare (<30 total), keep simple
                sel[sl] = j;
            } else if (v == T){
                if (slotT < need) sel[ng + slotT] = j;
                ++slotT;
            }
        }
        __syncthreads();
    }

    // ====== recurrent pointer-chase: 3 barriers/step, 1 atomic/warp =========
    for (int t = 0; t < KMAX; ++t){
        if (t >= kb) break;                           // uniform per block

        // Phase A (warp 0): dedup targets, rowbits from shared
        if (wid == 0){
            int an = (lane < CAPA) ? sel[lane] : 0;
            int tg = (lane < CAPA) ? sp[an / CAPA] : (256 + lane);
            unsigned mm = __match_any_sync(0xffffffffu, tg);
            if (lane < CAPA) arb[lane] = srb[an];     // LDS only
            bool leader = (lane < CAPA) && ((int)(__ffs(mm) - 1) == lane);
            unsigned lb = __ballot_sync(0xffffffffu, leader);
            if (leader){
                int pos = __popc(lb & ((1u << lane) - 1u));
                tgtl[pos]  = tg;
                smask[pos] = mm;                      // source set for this target
            }
            if (lane == 0){ sntgt = __popc(lb); sncand = 0; }
        }
        __syncthreads();

        // Phase B: warp handles targets {wid, wid+16}; ONE atomic per warp
        const int ntg = sntgt;
        {
            float vv1 = 0.f, vv2 = 0.f;
            int   j1 = 0, j2 = 0;
            bool  p1 = false, p2 = false;
            if (wid < ntg){
                int a = tgtl[wid];
                unsigned srcs = smask[wid];
                j1 = a * CAPA + lane;
                float ic = (lane < CAPA) ? sinvc[j1] : 0.f;
                while (srcs){                         // equal-term adds: order-free
                    int m = __ffs(srcs) - 1; srcs &= srcs - 1;
                    if ((arb[m] >> lane) & 1u) vv1 += ic;
                }
                p1 = (lane < CAPA) && (vv1 > 0.f);
            }
            if (wid + NWARP < ntg){
                int a = tgtl[wid + NWARP];
                unsigned srcs = smask[wid + NWARP];
                j2 = a * CAPA + lane;
                float ic = (lane < CAPA) ? sinvc[j2] : 0.f;
                while (srcs){
                    int m = __ffs(srcs) - 1; srcs &= srcs - 1;
                    if ((arb[m] >> lane) & 1u) vv2 += ic;
                }
                p2 = (lane < CAPA) && (vv2 > 0.f);
            }
            unsigned bal1 = __ballot_sync(0xffffffffu, p1);
            unsigned bal2 = __ballot_sync(0xffffffffu, p2);
            int tot = __popc(bal1) + __popc(bal2);
            int base = 0;
            if (lane == 0 && tot) base = atomicAdd(&sncand, tot);
            base = __shfl_sync(0xffffffffu, base, 0);
            unsigned ltm = (1u << lane) - 1u;
            if (p1) cand[base + __popc(bal1 & ltm)] = make_key(vv1, j1);
            if (p2) cand[base + __popc(bal1) + __popc(bal2 & ltm)] = make_key(vv2, j2);
        }
        __syncthreads();

        // Phase C: rank-select top-30 (+ smallest-index zero fill)
        const int nc = sncand;
        for (int q = tid; q < nc; q += NTM){
            unsigned long long kq = cand[q];
            int rank = 0;
            for (int x = 0; x < nc; ++x) rank += (cand[x] > kq);
            if (rank < CAPA) sel[rank] = key_j(kq);
        }
        if (tid == 0 && nc < CAPA){
            int P = nc, j = 0;
            while (P < CAPA){
                bool ispos = false;
                for (int x = 0; x < nc; ++x) ispos |= (key_j(cand[x]) == j);
                if (!ispos) sel[P++] = j;
                ++j;
            }
        }
        __syncthreads();
    }

    // ====== overlaps -> argmax (warp 0 reduce) -> one-hot ===================
    if (tid < NASM) scnt[tid] = 0;
    __syncthreads();
    if (tid < CAPA) atomicAdd(&scnt[sel[tid] / CAPA], 1);
    __syncthreads();
    if (wid == 0){
        unsigned long long bk = 0;
        #pragma unroll
        for (int r = 0; r < NASM / 32; ++r){
            int a = lane + r * 32;
            unsigned long long key =
                (((unsigned long long)scnt[a]) << 32) | (unsigned)(NASM - 1 - a);
            if (key > bk) bk = key;                   // max count, then smallest a
        }
        #pragma unroll
        for (int o = 16; o > 0; o >>= 1){
            unsigned long long obk = __shfl_xor_sync(0xffffffffu, bk, o);
            if (obk > bk) bk = obk;
        }
        if (lane == 0) sbesta = NASM - 1 - (int)(bk & 0xffffffffull);
    }
    __syncthreads();
    if (tid < NASM) out[(size_t)b * NASM + tid] = (tid == sbesta) ? 1.0f : 0.0f;
}

// ---------------------------------------------------------------------------
extern "C" void kernel_launch(void* const* d_in, const int* in_sizes, int n_in,
                              void* d_out, int out_size)
{
    const int*   p     = (const int*)d_in[0];     // [256]
    const int*   s     = (const int*)d_in[1];     // [64]
    const int*   k     = (const int*)d_in[2];     // [64]
    const float* W_in  = (const float*)d_in[3];   // [7680*7680]
    const float* W_rec = (const float*)d_in[4];   // [7680*7680]
    float*       out   = (float*)d_out;           // [64*256]

    cudaFuncSetAttribute(pointer_ac_kernel,
                         cudaFuncAttributeMaxDynamicSharedMemorySize, SMEM_DYN_BYTES);
    prep_kernel<<<S1BLK + NASM, 128>>>(p, s, W_in, W_rec);
    pointer_ac_kernel<<<BATCH, NTM, SMEM_DYN_BYTES>>>(p, s, k, out);
}

// round 17
// speedup vs baseline: 1.5892x; 1.1232x over previous
#include <cuda_runtime.h>
#include <cstdint>

#define NN     7680
#define NASM   256
#define CAPA   30
#define BATCH  64
#define KMAX   8
#define NTM    512
#define RPTM   15      // NN / NTM
#define NWARP  16
#define MAXC   960
#define S1BLK  960     // step1: 15 chunks x 64 samples
#define NN4    (NN / 4)
#define QCH    8       // colnorm source-chunk

// dynamic smem layout (bytes): [0,7680) cand/sc8 union, [7680,38400) sinvc,
// [38400,69120) srb
#define SMEM_DYN_BYTES (7680 + 30720 + 30720)

__device__ float         g_invc[NN];
__device__ unsigned char g_scores8[BATCH][NN];
__device__ unsigned int  g_rowbits[NN];

static __device__ __forceinline__ unsigned long long make_key(float v, int j){
    // v > 0. Bigger value -> bigger key; equal value -> smaller j wins.
    return (((unsigned long long)__float_as_uint(v)) << 32) | (unsigned int)(NN - 1 - j);
}
static __device__ __forceinline__ int key_j(unsigned long long k){
    return NN - 1 - (int)(k & 0xffffffffull);
}

// ---------------------------------------------------------------------------
// Fused prep (unchanged from R13 winner):
//  blocks [0,960):      step1 scores (uint8 exact counts), dedup by s[b]
//  blocks [960,1216):   colnorm + rowbits, gather-parallel
// ---------------------------------------------------------------------------
__global__ void __launch_bounds__(128) prep_kernel(
    const int* __restrict__ p, const int* __restrict__ s,
    const float* __restrict__ W_in, const float* __restrict__ W_rec)
{
    const int bid = blockIdx.x;
    const int tid = threadIdx.x;
    if (bid < S1BLK){
        __shared__ int ss[BATCH];
        const int b = bid / 15;
        if (tid < BATCH) ss[tid] = s[tid];
        __syncthreads();
        const int sb = ss[b];
        bool dup = false;
        for (int b2 = 0; b2 < b; ++b2) dup |= (ss[b2] == sb);
        if (dup) return;                              // representative writes instead

        const int c4 = (bid % 15) * 128 + tid;        // float4 index 0..1919
        const float4* src = (const float4*)(W_in + (size_t)sb * CAPA * NN) + c4;
        float ax = 0.f, ay = 0.f, az = 0.f, aw = 0.f;
        #pragma unroll 1
        for (int g = 0; g < 3; ++g){                  // 10 loads in flight per group
            float4 w[10];
            #pragma unroll
            for (int uu = 0; uu < 10; ++uu)
                w[uu] = __ldg(src + (size_t)(g * 10 + uu) * NN4);
            #pragma unroll
            for (int uu = 0; uu < 10; ++uu){          // integer counts: exact any order
                ax += w[uu].x; ay += w[uu].y; az += w[uu].z; aw += w[uu].w;
            }
        }
        uchar4 r;
        r.x = (unsigned char)(int)ax; r.y = (unsigned char)(int)ay;
        r.z = (unsigned char)(int)az; r.w = (unsigned char)(int)aw;
        ((uchar4*)g_scores8[b])[c4] = r;
    } else {
        // ---- colnorm + rowbits for destination assembly a ------------------
        __shared__ int      sp2[NASM];
        __shared__ int      qlist[NASM];
        __shared__ unsigned rbl[QCH * CAPA];
        __shared__ int      cnt[CAPA];
        __shared__ int      snq;
        const int a = bid - S1BLK;
        sp2[tid]       = p[tid];
        sp2[tid + 128] = p[tid + 128];
        if (tid < CAPA) cnt[tid] = 0;
        __syncthreads();
        if (tid < 32){                                // warp 0: sources pointing to a
            int run = 0;
            for (int g = 0; g < 8; ++g){
                bool m = (sp2[g * 32 + tid] == a);
                unsigned bal = __ballot_sync(0xffffffffu, m);
                if (m) qlist[run + __popc(bal & ((1u << tid) - 1u))] = g * 32 + tid;
                run += __popc(bal);
            }
            if (tid == 0) snq = run;
        }
        __syncthreads();
        const int nq = snq;
        for (int c0 = 0; c0 < nq; c0 += QCH){
            const int nqc   = min(QCH, nq - c0);
            const int tasks = nqc * CAPA;
            for (int i = tid; i < tasks; i += 128){
                int qi = i / CAPA, m = i % CAPA;
                int q  = qlist[c0 + qi];
                const float* row = W_rec + (size_t)(q * CAPA + m) * NN + a * CAPA;
                unsigned bits = 0;
                #pragma unroll
                for (int c = 0; c < CAPA; ++c)
                    if (row[c] != 0.f) bits |= (1u << c);
                rbl[i] = bits;
                g_rowbits[q * CAPA + m] = bits;
            }
            __syncthreads();
            if (tid < CAPA){
                int add = 0;
                for (int w = 0; w < tasks; ++w) add += (rbl[w] >> tid) & 1;
                cnt[tid] += add;
            }
            __syncthreads();
        }
        if (tid < CAPA) g_invc[a * CAPA + tid] = 1.0f / fmaxf((float)cnt[tid], 1e-6f);
    }
}

// ---------------------------------------------------------------------------
// Main: one block per sample; R13 winner structure; overlapped startup loads.
// ---------------------------------------------------------------------------
__global__ void __launch_bounds__(NTM) pointer_ac_kernel(
    const int* __restrict__ p, const int* __restrict__ s,
    const int* __restrict__ k, float* __restrict__ out)
{
    extern __shared__ char dyn[];
    unsigned long long* cand = (unsigned long long*)dyn;      // [MAXC], chase phase
    unsigned char*      sc8  = (unsigned char*)dyn;           // [NN], kWTA phase (union)
    float*              sinvc = (float*)(dyn + 7680);         // [NN]
    unsigned int*       srb   = (unsigned int*)(dyn + 38400); // [NN]

    __shared__ int   warpHist[NWARP * 31];
    __shared__ int   hist[31];
    __shared__ int   sp[NASM];
    __shared__ int   ssamp[BATCH];
    __shared__ int   scnt[NASM];
    __shared__ int   sel[CAPA];
    __shared__ int   tgtl[CAPA];
    __shared__ unsigned int smask[CAPA];
    __shared__ unsigned int arb[CAPA];
    __shared__ int   warpSum[NWARP], warpOff[NWARP];
    __shared__ int   sT, sNG, sticket, sncand, sntgt, sbesta;

    const int b    = blockIdx.x;
    const int tid  = threadIdx.x;
    const int lane = tid & 31;
    const int wid  = tid >> 5;

    if (tid < NASM) sp[tid] = p[tid];
    if (tid < BATCH) ssamp[tid] = s[tid];
    const int kb = __ldg(&k[b]);
    if (tid < NWARP * 31) warpHist[tid] = 0;
    if (tid == 0) sticket = 0;
    __syncthreads();                                  // ssamp ready (tiny barrier)

    // representative sample (first occurrence of s[b]) holds the scores
    int rep = b;
    for (int b2 = 0; b2 < BATCH; ++b2){
        if (ssamp[b2] == ssamp[b]){ rep = b2; break; }
    }

    // ALL big global loads issued in one overlapped window
    if (tid < NN / 16)                                // sc8: 480 uint4 (byte array)
        ((uint4*)sc8)[tid] = ((const uint4*)g_scores8[rep])[tid];
    #pragma unroll
    for (int r = 0; r < 4; ++r){                      // sinvc: 1920 float4
        int i = tid + r * NTM;
        if (i < NN4) ((float4*)sinvc)[i] = ((const float4*)g_invc)[i];
    }
    #pragma unroll
    for (int r = 0; r < 4; ++r){                      // srb: 1920 uint4
        int i = tid + r * NTM;
        if (i < NN4) ((uint4*)srb)[i] = ((const uint4*)g_rowbits)[i];
    }
    __syncthreads();

    // ====== dense kWTA via histogram (exact ints 0..30) =====================
    {
        int* myh = warpHist + wid * 31;
        const int base_j = tid * RPTM;                // contiguous segment
        #pragma unroll
        for (int i = 0; i < RPTM; ++i){
            int v = sc8[base_j + i];
            atomicAdd(&myh[v], 1);
        }
        __syncthreads();
        if (tid < 31){
            int c = 0;
            #pragma unroll
            for (int w = 0; w < NWARP; ++w) c += warpHist[w * 31 + tid];
            hist[tid] = c;
        }
        __syncthreads();
        if (tid == 0){
            int suf = 0, T = 0, ng = 0;
            for (int v = 30; v >= 0; --v){
                suf += hist[v];
                if (suf >= CAPA){ T = v; ng = suf - hist[v]; break; }
            }
            sT = T; sNG = ng;
        }
        __syncthreads();
        const int T    = sT;
        const int ng   = sNG;
        const int need = CAPA - ng;

        int cntT = 0;
        #pragma unroll
        for (int i = 0; i < RPTM; ++i) cntT += (sc8[base_j + i] == T);
        int incl = cntT;
        #pragma unroll
        for (int o = 1; o < 32; o <<= 1){
            int n = __shfl_up_sync(0xffffffffu, incl, o);
            if (lane >= o) incl += n;
        }
        if (lane == 31) warpSum[wid] = incl;
        __syncthreads();
        if (tid == 0){
            int run = 0;
            #pragma unroll
            for (int w = 0; w < NWARP; ++w){ warpOff[w] = run; run += warpSum[w]; }
        }
        __syncthreads();
        int slotT = warpOff[wid] + incl - cntT;

        #pragma unroll
        for (int i = 0; i < RPTM; ++i){
            int j = base_j + i;
            int v = sc8[j];
            if (v > T){
                int sl = atomicAdd(&sticket, 1);      // set order irrelevant
                sel[sl] = j;
            } else if (v == T){
                if (slotT < need) sel[ng + slotT] = j;
                ++slotT;
            }
        }
        __syncthreads();
    }

    // ====== recurrent pointer-chase: 3 light barriers per step ==============
    for (int t = 0; t < KMAX; ++t){
        if (t >= kb) break;                           // uniform per block

        // Phase A (warp 0): dedup targets, rowbits from shared
        if (wid == 0){
            int an = (lane < CAPA) ? sel[lane] : 0;
            int tg = (lane < CAPA) ? sp[an / CAPA] : (256 + lane);
            unsigned mm = __match_any_sync(0xffffffffu, tg);
            if (lane < CAPA) arb[lane] = srb[an];     // LDS only
            bool leader = (lane < CAPA) && ((int)(__ffs(mm) - 1) == lane);
            unsigned lb = __ballot_sync(0xffffffffu, leader);
            if (leader){
                int pos = __popc(lb & ((1u << lane) - 1u));
                tgtl[pos]  = tg;
                smask[pos] = mm;                      // source set for this target
            }
            if (lane == 0){ sntgt = __popc(lb); sncand = 0; }
        }
        __syncthreads();

        // Phase B: lane = column; warps stride over targets (<=30)
        const int ntg = sntgt;
        for (int idx = wid; idx < ntg; idx += NWARP){
            int a = tgtl[idx];
            unsigned srcs = smask[idx];
            int j = a * CAPA + lane;
            float ic = (lane < CAPA) ? sinvc[j] : 0.f;
            float vv = 0.f;
            while (srcs){                             // m ascending: same FP order
                int m = __ffs(srcs) - 1; srcs &= srcs - 1;
                if ((arb[m] >> lane) & 1u) vv += ic;  // lanes 30/31: bit always 0
            }
            bool pos = (lane < CAPA) && (vv > 0.f);
            unsigned bal = __ballot_sync(0xffffffffu, pos);
            if (bal){
                int ldr = __ffs(bal) - 1;
                int base = 0;
                if (lane == ldr) base = atomicAdd(&sncand, __popc(bal));
                base = __shfl_sync(0xffffffffu, base, ldr);
                if (pos) cand[base + __popc(bal & ((1u << lane) - 1u))] = make_key(vv, j);
            }
        }
        __syncthreads();

        // Phase C: rank-select top-30 (+ smallest-index zero fill)
        const int nc = sncand;
        for (int q = tid; q < nc; q += NTM){
            unsigned long long kq = cand[q];
            int rank = 0;
            for (int x = 0; x < nc; ++x) rank += (cand[x] > kq);
            if (rank < CAPA) sel[rank] = key_j(kq);
        }
        if (tid == 0 && nc < CAPA){
            int P = nc, j = 0;
            while (P < CAPA){
                bool ispos = false;
                for (int x = 0; x < nc; ++x) ispos |= (key_j(cand[x]) == j);
                if (!ispos) sel[P++] = j;
                ++j;
            }
        }
        __syncthreads();
    }

    // ====== overlaps -> argmax (warp 0 reduce) -> one-hot ===================
    if (tid < NASM) scnt[tid] = 0;
    __syncthreads();
    if (tid < CAPA) atomicAdd(&scnt[sel[tid] / CAPA], 1);
    __syncthreads();
    if (wid == 0){
        unsigned long long bk = 0;
        #pragma unroll
        for (int r = 0; r < NASM / 32; ++r){
            int a = lane + r * 32;
            unsigned long long key =
                (((unsigned long long)scnt[a]) << 32) | (unsigned)(NASM - 1 - a);
            if (key > bk) bk = key;                   // max count, then smallest a
        }
        #pragma unroll
        for (int o = 16; o > 0; o >>= 1){
            unsigned long long obk = __shfl_xor_sync(0xffffffffu, bk, o);
            if (obk > bk) bk = obk;
        }
        if (lane == 0) sbesta = NASM - 1 - (int)(bk & 0xffffffffull);
    }
    __syncthreads();
    if (tid < NASM) out[(size_t)b * NASM + tid] = (tid == sbesta) ? 1.0f : 0.0f;
}

// ---------------------------------------------------------------------------
extern "C" void kernel_launch(void* const* d_in, const int* in_sizes, int n_in,
                              void* d_out, int out_size)
{
    const int*   p     = (const int*)d_in[0];     // [256]
    const int*   s     = (const int*)d_in[1];     // [64]
    const int*   k     = (const int*)d_in[2];     // [64]
    const float* W_in  = (const float*)d_in[3];   // [7680*7680]
    const float* W_rec = (const float*)d_in[4];   // [7680*7680]
    float*       out   = (float*)d_out;           // [64*256]

    cudaFuncSetAttribute(pointer_ac_kernel,
                         cudaFuncAttributeMaxDynamicSharedMemorySize, SMEM_DYN_BYTES);
    prep_kernel<<<S1BLK + NASM, 128>>>(p, s, W_in, W_rec);
    pointer_ac_kernel<<<BATCH, NTM, SMEM_DYN_BYTES>>>(p, s, k, out);
}